// round 1
// baseline (speedup 1.0000x reference)
#include <cuda_runtime.h>
#include <math.h>

#define B_ROWS   512
#define T_STEPS  128
#define DIM_IN   256
#define HDIM     1024
#define FOURH    4096

#define BM 64
#define BN 64
#define BK 32
#define NTHREADS 256

// Persistent scratch (module-load allocated; zero-initialized once).
// h sequences use T+1 slots: slot 0 = zero initial hidden, h at time t -> slot t+1.
__device__ float g_h1[(size_t)(T_STEPS + 1) * B_ROWS * HDIM];
__device__ float g_h2[(size_t)(T_STEPS + 1) * B_ROWS * HDIM];
__device__ float g_c1[(size_t)B_ROWS * HDIM];
__device__ float g_c2[(size_t)B_ROWS * HDIM];

__device__ __forceinline__ float sigmoidf_(float x) {
    return 1.0f / (1.0f + __expf(-x));
}

// Fused LSTM step: z = X@W + Hprev@U + bias (4 gate tiles per block), then
// the cell update in the epilogue. Block tile: 64 rows x 64 cols x 4 gates.
__global__ __launch_bounds__(NTHREADS)
void lstm_step_kernel(const float* __restrict__ X, int ldx, int Kx,
                      const float* __restrict__ Hprev,
                      const float* __restrict__ W,      // [Kx, 4H]
                      const float* __restrict__ U,      // [H, 4H]
                      const float* __restrict__ bias,   // [4H]
                      float* __restrict__ C,            // [B, H] in/out
                      float* __restrict__ Hout,         // [B, H]
                      int first)
{
    __shared__ float As[BK][BM + 1];          // +1 pad: conflict-free transpose store
    __shared__ float Bs[4][BK][BN];           // 32 KB

    const int tid  = threadIdx.x;
    const int tx   = tid & 31;                // column-pair index
    const int ty   = tid >> 5;                // row group (warp id)
    const int row0 = blockIdx.y * BM;
    const int col0 = blockIdx.x * BN;
    const int c0   = tx * 2;

    float acc[4][8][2];
    #pragma unroll
    for (int g = 0; g < 4; ++g)
        #pragma unroll
        for (int i = 0; i < 8; ++i) { acc[g][i][0] = 0.f; acc[g][i][1] = 0.f; }

    const int nseg = first ? 1 : 2;
    for (int seg = 0; seg < nseg; ++seg) {
        const float* Ap  = (seg == 0) ? X   : Hprev;
        const int    lda = (seg == 0) ? ldx : HDIM;
        const float* Bp  = (seg == 0) ? W   : U;
        const int   Kseg = (seg == 0) ? Kx  : HDIM;

        for (int k0 = 0; k0 < Kseg; k0 += BK) {
            // Load A tile [BM x BK], store transposed As[kk][r]
            #pragma unroll
            for (int idx = tid; idx < BM * BK; idx += NTHREADS) {
                int r  = idx >> 5;
                int kk = idx & 31;
                As[kk][r] = Ap[(size_t)(row0 + r) * lda + k0 + kk];
            }
            // Load B tiles for all 4 gates [4 x BK x BN]
            #pragma unroll
            for (int idx = tid; idx < 4 * BK * BN; idx += NTHREADS) {
                int g  = idx >> 11;          // / (BK*BN)
                int kk = (idx >> 6) & 31;    // / BN % BK
                int c  = idx & 63;
                Bs[g][kk][c] = Bp[(size_t)(k0 + kk) * FOURH + g * HDIM + col0 + c];
            }
            __syncthreads();

            #pragma unroll
            for (int kk = 0; kk < BK; ++kk) {
                float a[8];
                #pragma unroll
                for (int i = 0; i < 8; ++i) a[i] = As[kk][ty * 8 + i];  // warp-broadcast
                #pragma unroll
                for (int g = 0; g < 4; ++g) {
                    float b0 = Bs[g][kk][c0];
                    float b1 = Bs[g][kk][c0 + 1];
                    #pragma unroll
                    for (int i = 0; i < 8; ++i) {
                        acc[g][i][0] = fmaf(a[i], b0, acc[g][i][0]);
                        acc[g][i][1] = fmaf(a[i], b1, acc[g][i][1]);
                    }
                }
            }
            __syncthreads();
        }
    }

    // Epilogue: keras gate order (i, f, g, o); c' = f*c + i*tanh(g); h = o*tanh(c')
    #pragma unroll
    for (int i = 0; i < 8; ++i) {
        const int r = row0 + ty * 8 + i;
        #pragma unroll
        for (int j = 0; j < 2; ++j) {
            const int jh = col0 + c0 + j;
            float zi = acc[0][i][j] + bias[jh];
            float zf = acc[1][i][j] + bias[HDIM + jh];
            float zg = acc[2][i][j] + bias[2 * HDIM + jh];
            float zo = acc[3][i][j] + bias[3 * HDIM + jh];
            float ig = sigmoidf_(zi);
            float fg = sigmoidf_(zf);
            float gg = tanhf(zg);
            float og = sigmoidf_(zo);
            size_t off = (size_t)r * HDIM + jh;
            float cold = first ? 0.f : C[off];
            float cn = fmaf(fg, cold, ig * gg);
            C[off]    = cn;
            Hout[off] = og * tanhf(cn);
        }
    }
}

// Gather last valid hidden state per sequence, tiny dense (1024 -> 3) + relu.
__global__ void dense_kernel(const float* __restrict__ h2seq,
                             const int* __restrict__ seqlen,
                             const float* __restrict__ Wd,   // [H, 3]
                             const float* __restrict__ bd,   // [3]
                             float* __restrict__ out)        // [B, 3]
{
    const int b = blockIdx.x;
    const int slot = seqlen[b];  // h at t = seqlen-1 lives in slot seqlen
    const float* h = h2seq + (size_t)slot * B_ROWS * HDIM + (size_t)b * HDIM;

    float s0 = 0.f, s1 = 0.f, s2 = 0.f;
    for (int k = threadIdx.x; k < HDIM; k += blockDim.x) {
        float hv = h[k];
        s0 = fmaf(hv, Wd[k * 3 + 0], s0);
        s1 = fmaf(hv, Wd[k * 3 + 1], s1);
        s2 = fmaf(hv, Wd[k * 3 + 2], s2);
    }
    #pragma unroll
    for (int o = 16; o > 0; o >>= 1) {
        s0 += __shfl_down_sync(0xffffffffu, s0, o);
        s1 += __shfl_down_sync(0xffffffffu, s1, o);
        s2 += __shfl_down_sync(0xffffffffu, s2, o);
    }
    __shared__ float red[8][3];
    const int wid = threadIdx.x >> 5, lane = threadIdx.x & 31;
    if (lane == 0) { red[wid][0] = s0; red[wid][1] = s1; red[wid][2] = s2; }
    __syncthreads();
    if (threadIdx.x == 0) {
        float r0 = 0.f, r1 = 0.f, r2 = 0.f;
        const int nw = blockDim.x >> 5;
        for (int w = 0; w < nw; ++w) { r0 += red[w][0]; r1 += red[w][1]; r2 += red[w][2]; }
        out[b * 3 + 0] = fmaxf(r0 + bd[0], 0.f);
        out[b * 3 + 1] = fmaxf(r1 + bd[1], 0.f);
        out[b * 3 + 2] = fmaxf(r2 + bd[2], 0.f);
    }
}

extern "C" void kernel_launch(void* const* d_in, const int* in_sizes, int n_in,
                              void* d_out, int out_size) {
    const float* chars  = (const float*)d_in[0];  // [B, T, 256]
    const int*   seqlen = (const int*)  d_in[1];  // [B]
    const float* W1 = (const float*)d_in[2];      // [256, 4096]
    const float* U1 = (const float*)d_in[3];      // [1024, 4096]
    const float* b1 = (const float*)d_in[4];      // [4096]
    const float* W2 = (const float*)d_in[5];      // [1024, 4096]
    const float* U2 = (const float*)d_in[6];      // [1024, 4096]
    const float* b2 = (const float*)d_in[7];      // [4096]
    const float* Wd = (const float*)d_in[8];      // [1024, 3]
    const float* bd = (const float*)d_in[9];      // [3]
    float* out = (float*)d_out;

    float *h1, *h2, *c1, *c2;
    cudaGetSymbolAddress((void**)&h1, g_h1);
    cudaGetSymbolAddress((void**)&h2, g_h2);
    cudaGetSymbolAddress((void**)&c1, g_c1);
    cudaGetSymbolAddress((void**)&c2, g_c2);

    const dim3 grid(HDIM / BN, B_ROWS / BM);
    const size_t SLOT = (size_t)B_ROWS * HDIM;

    // Layer 1: x_t from chars (row stride T*D_IN), K = 256
    for (int t = 0; t < T_STEPS; ++t) {
        lstm_step_kernel<<<grid, NTHREADS>>>(
            chars + (size_t)t * DIM_IN, T_STEPS * DIM_IN, DIM_IN,
            h1 + (size_t)t * SLOT,
            W1, U1, b1, c1,
            h1 + (size_t)(t + 1) * SLOT,
            t == 0 ? 1 : 0);
    }
    // Layer 2: x_t = h1 at time t (slot t+1), K = 1024
    for (int t = 0; t < T_STEPS; ++t) {
        lstm_step_kernel<<<grid, NTHREADS>>>(
            h1 + (size_t)(t + 1) * SLOT, HDIM, HDIM,
            h2 + (size_t)t * SLOT,
            W2, U2, b2, c2,
            h2 + (size_t)(t + 1) * SLOT,
            t == 0 ? 1 : 0);
    }
    dense_kernel<<<B_ROWS, 256>>>(h2, seqlen, Wd, bd, out);
}

// round 4
// speedup vs baseline: 2.2039x; 2.2039x over previous
#include <cuda_runtime.h>
#include <cuda_bf16.h>
#include <cstdint>
#include <math.h>

typedef __nv_bfloat16 bf16;

#define B_ROWS   512
#define T_STEPS  128
#define DIM_IN   256
#define HDIM     1024
#define FOURH    4096

#define BM 64
#define BN 64            // columns per gate per block
#define NTH 256

// smem layout (bytes). Rows are 32 bf16 of data in a 40-bf16 (80B) stride:
// 8 consecutive ldmatrix row addresses at stride 80B hit distinct 16B banks.
#define A_PLANE_B (64 * 80)            // 5120
#define A_BUF_B   (2 * A_PLANE_B)      // hi+lo
#define B_PLANE_B (256 * 80)           // 20480
#define B_BUF_B   (2 * B_PLANE_B)
#define SM_A_OFF(buf) ((buf) * A_BUF_B)
#define SM_B_OFF(buf) (2 * A_BUF_B + (buf) * B_BUF_B)
#define SMEM_BYTES (2 * A_BUF_B + 2 * B_BUF_B)   // 102400

// ---------------- persistent device scratch ----------------
__device__ bf16  g_h1hi[2][B_ROWS * HDIM];
__device__ bf16  g_h1lo[2][B_ROWS * HDIM];
__device__ bf16  g_h2hi[2][B_ROWS * HDIM];
__device__ bf16  g_h2lo[2][B_ROWS * HDIM];
__device__ float g_c1[(size_t)B_ROWS * HDIM];
__device__ float g_c2[(size_t)B_ROWS * HDIM];
__device__ float g_hfinal[(size_t)B_ROWS * HDIM];
__device__ bf16  g_xhi[(size_t)B_ROWS * T_STEPS * DIM_IN];
__device__ bf16  g_xlo[(size_t)B_ROWS * T_STEPS * DIM_IN];
// transposed split weights: row = gate*1024 + n, K-major
__device__ bf16  g_w1hi[(size_t)FOURH * DIM_IN],  g_w1lo[(size_t)FOURH * DIM_IN];
__device__ bf16  g_u1hi[(size_t)FOURH * HDIM],    g_u1lo[(size_t)FOURH * HDIM];
__device__ bf16  g_w2hi[(size_t)FOURH * HDIM],    g_w2lo[(size_t)FOURH * HDIM];
__device__ bf16  g_u2hi[(size_t)FOURH * HDIM],    g_u2lo[(size_t)FOURH * HDIM];

// ---------------- helpers ----------------
__device__ __forceinline__ uint32_t smem_u32(const void* p) {
    uint32_t a;
    asm("{ .reg .u64 t; cvta.to.shared.u64 t, %1; cvt.u32.u64 %0, t; }" : "=r"(a) : "l"(p));
    return a;
}
__device__ __forceinline__ void cp16(uint32_t s, const void* g) {
    asm volatile("cp.async.cg.shared.global [%0], [%1], 16;" :: "r"(s), "l"(g));
}
__device__ __forceinline__ void cp_commit() { asm volatile("cp.async.commit_group;" ::: "memory"); }
__device__ __forceinline__ void cp_wait1()  { asm volatile("cp.async.wait_group 1;" ::: "memory"); }
__device__ __forceinline__ void cp_wait0()  { asm volatile("cp.async.wait_group 0;" ::: "memory"); }
__device__ __forceinline__ void ldmx4(uint32_t* r, uint32_t a) {
    asm volatile("ldmatrix.sync.aligned.m8n8.x4.shared.b16 {%0,%1,%2,%3}, [%4];"
                 : "=r"(r[0]), "=r"(r[1]), "=r"(r[2]), "=r"(r[3]) : "r"(a));
}
__device__ __forceinline__ void ldmx2(uint32_t* r, uint32_t a) {
    asm volatile("ldmatrix.sync.aligned.m8n8.x2.shared.b16 {%0,%1}, [%2];"
                 : "=r"(r[0]), "=r"(r[1]) : "r"(a));
}
__device__ __forceinline__ void mma_bf16(float* d, const uint32_t* a, const uint32_t* b) {
    asm volatile(
        "mma.sync.aligned.m16n8k16.row.col.f32.bf16.bf16.f32 "
        "{%0,%1,%2,%3}, {%4,%5,%6,%7}, {%8,%9}, {%0,%1,%2,%3};"
        : "+f"(d[0]), "+f"(d[1]), "+f"(d[2]), "+f"(d[3])
        : "r"(a[0]), "r"(a[1]), "r"(a[2]), "r"(a[3]), "r"(b[0]), "r"(b[1]));
}
__device__ __forceinline__ float fsig(float x) { return 1.0f / (1.0f + __expf(-x)); }
__device__ __forceinline__ void split_bf16(float x, bf16& hi, bf16& lo) {
    hi = __float2bfloat16(x);
    lo = __float2bfloat16(x - __bfloat162float(hi));
}

// ---------------- prep kernels ----------------
__global__ void split_chars(const float* __restrict__ x,
                            bf16* __restrict__ hi, bf16* __restrict__ lo, int n) {
    int i = blockIdx.x * blockDim.x + threadIdx.x;
    if (i < n) { bf16 h, l; split_bf16(x[i], h, l); hi[i] = h; lo[i] = l; }
}

// W[K][4096] fp32 -> Whi/Wlo[n4][K] bf16 (n4 = gate*1024 + n)
__global__ void transpose_split_w(const float* __restrict__ W,
                                  bf16* __restrict__ Whi, bf16* __restrict__ Wlo, int K) {
    __shared__ float tile[32][33];
    int nb = blockIdx.x * 32, kb = blockIdx.y * 32;
    int x = threadIdx.x, y = threadIdx.y;
    #pragma unroll
    for (int yy = y; yy < 32; yy += 8)
        tile[yy][x] = W[(size_t)(kb + yy) * FOURH + nb + x];
    __syncthreads();
    #pragma unroll
    for (int yy = y; yy < 32; yy += 8) {
        float w = tile[x][yy];
        bf16 h, l; split_bf16(w, h, l);
        size_t o = (size_t)(nb + yy) * K + kb + x;
        Whi[o] = h; Wlo[o] = l;
    }
}

// ---------------- fused LSTM step (bf16x3 mma.sync) ----------------
__global__ __launch_bounds__(NTH, 1)
void lstm_step(const bf16* __restrict__ Xhi, const bf16* __restrict__ Xlo,
               size_t xstride, int Kx,
               const bf16* __restrict__ Hhi, const bf16* __restrict__ Hlo,
               const bf16* __restrict__ Whi, const bf16* __restrict__ Wlo,
               const bf16* __restrict__ Uhi, const bf16* __restrict__ Ulo,
               const float* __restrict__ bias,
               float* __restrict__ C,
               bf16* __restrict__ Ohi, bf16* __restrict__ Olo,
               const int* __restrict__ seqlen, float* __restrict__ hfinal, int t,
               int first)
{
    extern __shared__ char smemc[];
    const uint32_t sb = smem_u32(smemc);
    const int tid  = threadIdx.x;
    const int lane = tid & 31;
    const int warp = tid >> 5;
    const int wm   = warp >> 2;          // 0..1 -> 32-row slab
    const int wn   = warp & 3;           // 0..3 -> 16-col slab
    const int n0   = blockIdx.x * BN;
    const int row0 = blockIdx.y * BM;

    // ldmatrix lane address components
    const int arow  = (lane & 7) + ((lane >> 3) & 1) * 8;
    const int koffA = (lane >> 4) * 8;
    const int laneb = lane & 15;
    const int brow  = laneb & 7;
    const int koffB = ((laneb >> 3) & 1) * 8;

    float acc[4][2][2][4];
    #pragma unroll
    for (int g = 0; g < 4; ++g)
        #pragma unroll
        for (int mt = 0; mt < 2; ++mt)
            #pragma unroll
            for (int nt = 0; nt < 2; ++nt)
                #pragma unroll
                for (int q = 0; q < 4; ++q) acc[g][mt][nt][q] = 0.f;

    const int c0n = Kx >> 5;
    const int nch = first ? c0n : (c0n + (HDIM >> 5));

    auto load_chunk = [&](int c, int buf) {
        const int seg = (c < c0n) ? 0 : 1;
        const int k0  = ((seg == 0) ? c : (c - c0n)) << 5;
        const bf16* Ah = (seg == 0) ? Xhi : Hhi;
        const bf16* Al = (seg == 0) ? Xlo : Hlo;
        const size_t astr = (seg == 0) ? xstride : (size_t)HDIM;
        const bf16* Bh = (seg == 0) ? Whi : Uhi;
        const bf16* Bl = (seg == 0) ? Wlo : Ulo;
        const int   Kb = (seg == 0) ? Kx : HDIM;
        // A: 2 planes x 64 rows x 4 cp16  (512 ops)
        #pragma unroll
        for (int j = 0; j < 2; ++j) {
            int u = j * NTH + tid;
            int pl = u >> 8, rem = u & 255, r = rem >> 2, q = rem & 3;
            const bf16* src = (pl ? Al : Ah) + (size_t)(row0 + r) * astr + k0 + q * 8;
            cp16(sb + SM_A_OFF(buf) + pl * A_PLANE_B + r * 80 + q * 16, src);
        }
        // B: 2 planes x 256 rows x 4 cp16 (2048 ops)
        #pragma unroll
        for (int j = 0; j < 8; ++j) {
            int u = j * NTH + tid;
            int pl = u >> 10, rem = u & 1023, r = rem >> 2, q = rem & 3;
            int n4 = ((r >> 6) << 10) + n0 + (r & 63);
            const bf16* src = (pl ? Bl : Bh) + (size_t)n4 * Kb + k0 + q * 8;
            cp16(sb + SM_B_OFF(buf) + pl * B_PLANE_B + r * 80 + q * 16, src);
        }
        cp_commit();
    };

    load_chunk(0, 0);
    if (nch > 1) load_chunk(1, 1);

    for (int i = 0; i < nch; ++i) {
        if (i + 1 < nch) cp_wait1(); else cp_wait0();
        __syncthreads();
        const int buf = i & 1;
        const uint32_t aB = sb + SM_A_OFF(buf);
        const uint32_t bB = sb + SM_B_OFF(buf);

        #pragma unroll
        for (int ks = 0; ks < 2; ++ks) {
            uint32_t ah[2][4], al[2][4];
            #pragma unroll
            for (int mt = 0; mt < 2; ++mt) {
                uint32_t aa = aB + (uint32_t)((wm * 32 + mt * 16 + arow) * 80
                                              + (ks * 16 + koffA) * 2);
                ldmx4(ah[mt], aa);
                ldmx4(al[mt], aa + A_PLANE_B);
            }
            #pragma unroll
            for (int g = 0; g < 4; ++g) {
                #pragma unroll
                for (int nt = 0; nt < 2; ++nt) {
                    uint32_t ba = bB + (uint32_t)((g * 64 + wn * 16 + nt * 8 + brow) * 80
                                                  + (ks * 16 + koffB) * 2);
                    uint32_t bh[2], bl[2];
                    ldmx2(bh, ba);
                    ldmx2(bl, ba + B_PLANE_B);
                    #pragma unroll
                    for (int mt = 0; mt < 2; ++mt) {
                        mma_bf16(acc[g][mt][nt], ah[mt], bh);
                        mma_bf16(acc[g][mt][nt], ah[mt], bl);
                        mma_bf16(acc[g][mt][nt], al[mt], bh);
                    }
                }
            }
        }
        __syncthreads();
        if (i + 2 < nch) load_chunk(i + 2, buf);
    }

    // ---- fused LSTM cell epilogue ----
    #pragma unroll
    for (int mt = 0; mt < 2; ++mt) {
        #pragma unroll
        for (int half = 0; half < 2; ++half) {
            const int r = row0 + wm * 32 + mt * 16 + half * 8 + (lane >> 2);
            const int slen = seqlen ? seqlen[r] : 0;
            #pragma unroll
            for (int nt = 0; nt < 2; ++nt) {
                const int c = n0 + wn * 16 + nt * 8 + (lane & 3) * 2;
                float2 cold = make_float2(0.f, 0.f);
                if (!first)
                    cold = *reinterpret_cast<const float2*>(C + (size_t)r * HDIM + c);
                float cn[2], hn[2];
                #pragma unroll
                for (int j = 0; j < 2; ++j) {
                    const int q = half * 2 + j;
                    float zi = acc[0][mt][nt][q] + bias[c + j];
                    float zf = acc[1][mt][nt][q] + bias[HDIM + c + j];
                    float zg = acc[2][mt][nt][q] + bias[2 * HDIM + c + j];
                    float zo = acc[3][mt][nt][q] + bias[3 * HDIM + c + j];
                    float ig = fsig(zi), fg = fsig(zf);
                    float gg = tanhf(zg), og = fsig(zo);
                    float co = (j == 0) ? cold.x : cold.y;
                    cn[j] = fmaf(fg, co, ig * gg);
                    hn[j] = og * tanhf(cn[j]);
                }
                *reinterpret_cast<float2*>(C + (size_t)r * HDIM + c) = make_float2(cn[0], cn[1]);
                bf16 h0, l0, h1, l1;
                split_bf16(hn[0], h0, l0);
                split_bf16(hn[1], h1, l1);
                *reinterpret_cast<__nv_bfloat162*>(Ohi + (size_t)r * HDIM + c) =
                    __nv_bfloat162(h0, h1);
                *reinterpret_cast<__nv_bfloat162*>(Olo + (size_t)r * HDIM + c) =
                    __nv_bfloat162(l0, l1);
                if (hfinal && slen - 1 == t)
                    *reinterpret_cast<float2*>(hfinal + (size_t)r * HDIM + c) =
                        make_float2(hn[0], hn[1]);
            }
        }
    }
}

// ---------------- final dense(1024->3) + relu ----------------
__global__ void dense_kernel(const float* __restrict__ hfinal,
                             const float* __restrict__ Wd,
                             const float* __restrict__ bd,
                             float* __restrict__ out)
{
    const int b = blockIdx.x;
    const float* h = hfinal + (size_t)b * HDIM;

    float s0 = 0.f, s1 = 0.f, s2 = 0.f;
    for (int k = threadIdx.x; k < HDIM; k += blockDim.x) {
        float hv = h[k];
        s0 = fmaf(hv, Wd[k * 3 + 0], s0);
        s1 = fmaf(hv, Wd[k * 3 + 1], s1);
        s2 = fmaf(hv, Wd[k * 3 + 2], s2);
    }
    #pragma unroll
    for (int o = 16; o > 0; o >>= 1) {
        s0 += __shfl_down_sync(0xffffffffu, s0, o);
        s1 += __shfl_down_sync(0xffffffffu, s1, o);
        s2 += __shfl_down_sync(0xffffffffu, s2, o);
    }
    __shared__ float red[8][3];
    const int wid = threadIdx.x >> 5, lane = threadIdx.x & 31;
    if (lane == 0) { red[wid][0] = s0; red[wid][1] = s1; red[wid][2] = s2; }
    __syncthreads();
    if (threadIdx.x == 0) {
        float r0 = 0.f, r1 = 0.f, r2 = 0.f;
        const int nw = blockDim.x >> 5;
        for (int w = 0; w < nw; ++w) { r0 += red[w][0]; r1 += red[w][1]; r2 += red[w][2]; }
        out[b * 3 + 0] = fmaxf(r0 + bd[0], 0.f);
        out[b * 3 + 1] = fmaxf(r1 + bd[1], 0.f);
        out[b * 3 + 2] = fmaxf(r2 + bd[2], 0.f);
    }
}

extern "C" void kernel_launch(void* const* d_in, const int* in_sizes, int n_in,
                              void* d_out, int out_size) {
    const float* chars  = (const float*)d_in[0];
    const int*   seqlen = (const int*)  d_in[1];
    const float* W1 = (const float*)d_in[2];
    const float* U1 = (const float*)d_in[3];
    const float* b1 = (const float*)d_in[4];
    const float* W2 = (const float*)d_in[5];
    const float* U2 = (const float*)d_in[6];
    const float* b2 = (const float*)d_in[7];
    const float* Wd = (const float*)d_in[8];
    const float* bd = (const float*)d_in[9];
    float* out = (float*)d_out;

    bf16 *h1hi, *h1lo, *h2hi, *h2lo, *xhi, *xlo;
    bf16 *w1hi, *w1lo, *u1hi, *u1lo, *w2hi, *w2lo, *u2hi, *u2lo;
    float *c1, *c2, *hfin;
    cudaGetSymbolAddress((void**)&h1hi, g_h1hi);
    cudaGetSymbolAddress((void**)&h1lo, g_h1lo);
    cudaGetSymbolAddress((void**)&h2hi, g_h2hi);
    cudaGetSymbolAddress((void**)&h2lo, g_h2lo);
    cudaGetSymbolAddress((void**)&c1,   g_c1);
    cudaGetSymbolAddress((void**)&c2,   g_c2);
    cudaGetSymbolAddress((void**)&hfin, g_hfinal);
    cudaGetSymbolAddress((void**)&xhi,  g_xhi);
    cudaGetSymbolAddress((void**)&xlo,  g_xlo);
    cudaGetSymbolAddress((void**)&w1hi, g_w1hi);
    cudaGetSymbolAddress((void**)&w1lo, g_w1lo);
    cudaGetSymbolAddress((void**)&u1hi, g_u1hi);
    cudaGetSymbolAddress((void**)&u1lo, g_u1lo);
    cudaGetSymbolAddress((void**)&w2hi, g_w2hi);
    cudaGetSymbolAddress((void**)&w2lo, g_w2lo);
    cudaGetSymbolAddress((void**)&u2hi, g_u2hi);
    cudaGetSymbolAddress((void**)&u2lo, g_u2lo);

    cudaFuncSetAttribute(lstm_step,
                         cudaFuncAttributeMaxDynamicSharedMemorySize, SMEM_BYTES);

    // prep: split chars + weights (per replay, deterministic)
    const int nx = B_ROWS * T_STEPS * DIM_IN;
    split_chars<<<(nx + 255) / 256, 256>>>(chars, xhi, xlo, nx);
    const dim3 tb(32, 8);
    transpose_split_w<<<dim3(FOURH / 32, DIM_IN / 32), tb>>>(W1, w1hi, w1lo, DIM_IN);
    transpose_split_w<<<dim3(FOURH / 32, HDIM  / 32), tb>>>(U1, u1hi, u1lo, HDIM);
    transpose_split_w<<<dim3(FOURH / 32, HDIM  / 32), tb>>>(W2, w2hi, w2lo, HDIM);
    transpose_split_w<<<dim3(FOURH / 32, HDIM  / 32), tb>>>(U2, u2hi, u2lo, HDIM);

    const dim3 grid(HDIM / BN, B_ROWS / BM);   // (16, 8)
    const size_t SLOT = (size_t)B_ROWS * HDIM;

    for (int t = 0; t < T_STEPS; ++t) {
        const int prev = t & 1, cur = (t + 1) & 1;
        const int first = (t == 0) ? 1 : 0;
        // layer 1
        lstm_step<<<grid, NTH, SMEM_BYTES>>>(
            xhi + (size_t)t * DIM_IN, xlo + (size_t)t * DIM_IN,
            (size_t)(T_STEPS * DIM_IN), DIM_IN,
            h1hi + prev * SLOT, h1lo + prev * SLOT,
            w1hi, w1lo, u1hi, u1lo,
            b1, c1,
            h1hi + cur * SLOT, h1lo + cur * SLOT,
            (const int*)nullptr, (float*)nullptr, t, first);
        // layer 2 (consumes layer-1 output of the same step)
        lstm_step<<<grid, NTH, SMEM_BYTES>>>(
            h1hi + cur * SLOT, h1lo + cur * SLOT,
            (size_t)HDIM, HDIM,
            h2hi + prev * SLOT, h2lo + prev * SLOT,
            w2hi, w2lo, u2hi, u2lo,
            b2, c2,
            h2hi + cur * SLOT, h2lo + cur * SLOT,
            seqlen, hfin, t, first);
    }
    dense_kernel<<<B_ROWS, 256>>>(hfin, Wd, bd, out);
}